// round 1
// baseline (speedup 1.0000x reference)
#include <cuda_runtime.h>
#include <math.h>

// ---------------- problem constants ----------------
#define TT      4000          // N_WORDS (sequence length)
#define NCHARS  16000
#define DCHAR   768
#define HH      400           // hidden size
#define KCTA    50            // CTAs per LSTM direction
#define HS      8             // h elements per CTA (400/50)
#define RPW     4             // gate rows per warp (32 rows / 8 warps)
#define NT      256           // threads per CTA (recurrence + gemm)

// ---------------- device scratch (static, no allocation) ----------------
__device__ float g_ef[TT * 868];        // [wc(768) | pos(100)]
__device__ float g_l1[TT * 800];        // layer-1 output [f1 | flip(f2)]
__device__ float g_PF[TT * 1600];       // x-projection, forward dir
__device__ float g_PB[TT * 1600];       // x-projection, backward dir
__device__ float g_mean[TT * DCHAR];    // chars_mean
__device__ int   g_starts[TT + 1];
__device__ int   g_cnt[4 * TT];         // per-step arrival counters (2 phases x 2 dirs)

// ---------------- small prep kernels ----------------
__global__ void k_zero_cnt() {
    int i = blockIdx.x * blockDim.x + threadIdx.x;
    if (i < 4 * TT) g_cnt[i] = 0;
}

__global__ void k_starts(const int* __restrict__ seg) {
    int i = blockIdx.x * blockDim.x + threadIdx.x;
    if (i < NCHARS) {
        if (i == 0 || seg[i] != seg[i - 1]) g_starts[seg[i]] = i;
    }
    if (i == 0) g_starts[TT] = NCHARS;
}

// chars = char_seq_embeds[1:-1]; per-word mean over contiguous (sorted) segments
__global__ void k_mean(const float* __restrict__ chem) {
    int w = blockIdx.x;
    int s = g_starts[w], e = g_starts[w + 1];
    float inv = 1.f / (float)(e - s);
    for (int d = threadIdx.x; d < DCHAR; d += blockDim.x) {
        float acc = 0.f;
        for (int r = s; r < e; r++) acc += chem[(r + 1) * DCHAR + d];
        g_mean[w * DCHAR + d] = acc * inv;
    }
}

__global__ void k_pos(const int* __restrict__ pos_seq, const float* __restrict__ pos_table) {
    int i = blockIdx.x * blockDim.x + threadIdx.x;
    if (i < TT * 100) {
        int m = i / 100, j = i % 100;
        g_ef[m * 868 + 768 + j] = pos_table[pos_seq[m] * 100 + j];
    }
}

// ---------------- generic fp32 GEMM:  C[m,n] = dot(A[m,:], B[n,:]) + bias[n] ----------------
// Tiles 64x64x16, 256 threads, 4x4 microtile. blockIdx.z selects weight-set {0,1}.
// mode==1: C = tanh(acc + bias) + extra[m*768+n]   (wc epilogue)
__global__ void __launch_bounds__(256) k_gemm(
    int M, int N, int Ka,
    const float* __restrict__ A, int lda, const int* __restrict__ Aidx,
    const float* __restrict__ B0, const float* __restrict__ bias0, float* __restrict__ C0,
    const float* __restrict__ B1, const float* __restrict__ bias1, float* __restrict__ C1,
    int ldc, const float* __restrict__ extra, int mode)
{
    const float* B = B0; const float* bias = bias0; float* C = C0;
    if (blockIdx.z) { B = B1; bias = bias1; C = C1; }

    __shared__ float As[16][65];
    __shared__ float Bs[16][64];
    int tid = threadIdx.x;
    int tx = tid & 15, ty = tid >> 4;
    int m0 = blockIdx.y * 64, n0 = blockIdx.x * 64;

    float acc[4][4];
#pragma unroll
    for (int i = 0; i < 4; i++)
#pragma unroll
        for (int j = 0; j < 4; j++) acc[i][j] = 0.f;

    for (int kt = 0; kt < Ka; kt += 16) {
        {   // load A tile (coalesced over k)
            int k = tid & 15, mm = tid >> 4;
#pragma unroll
            for (int i = 0; i < 4; i++) {
                int m = mm + i * 16; int gm = m0 + m; float v = 0.f;
                if (gm < M && kt + k < Ka) {
                    int ar = Aidx ? Aidx[gm] : gm;
                    v = A[ar * lda + kt + k];
                }
                As[k][m] = v;
            }
        }
        {   // load B tile
            int n = tid & 63, kq = tid >> 6;
#pragma unroll
            for (int i = 0; i < 4; i++) {
                int k = kq * 4 + i; float v = 0.f;
                if (kt + k < Ka) v = B[(n0 + n) * Ka + kt + k];
                Bs[k][n] = v;
            }
        }
        __syncthreads();
#pragma unroll
        for (int kk = 0; kk < 16; kk++) {
            float a[4], b[4];
#pragma unroll
            for (int i = 0; i < 4; i++) a[i] = As[kk][ty * 4 + i];
#pragma unroll
            for (int j = 0; j < 4; j++) b[j] = Bs[kk][tx * 4 + j];
#pragma unroll
            for (int i = 0; i < 4; i++)
#pragma unroll
                for (int j = 0; j < 4; j++) acc[i][j] += a[i] * b[j];
        }
        __syncthreads();
    }
#pragma unroll
    for (int i = 0; i < 4; i++) {
        int m = m0 + ty * 4 + i;
        if (m < M) {
#pragma unroll
            for (int j = 0; j < 4; j++) {
                int n = n0 + tx * 4 + j;
                float v = acc[i][j] + bias[n];
                if (mode == 1) v = tanhf(v) + extra[m * DCHAR + n];
                C[m * ldc + n] = v;
            }
        }
    }
}

// ---------------- persistent bidirectional LSTM recurrence ----------------
__device__ __forceinline__ float sigf(float x)  { return 1.f / (1.f + __expf(-x)); }
__device__ __forceinline__ float tanhff(float x){ return 2.f / (1.f + __expf(-2.f * x)) - 1.f; }

__device__ __forceinline__ int ld_acq(const int* p) {
    int v;
    asm volatile("ld.acquire.gpu.global.b32 %0, [%1];" : "=r"(v) : "l"(p) : "memory");
    return v;
}
__device__ __forceinline__ void red_rel(int* p) {
    asm volatile("red.release.gpu.global.add.s32 [%0], 1;" :: "l"(p) : "memory");
}

// grid = 2*KCTA CTAs (fwd dir first, then bwd dir), all co-resident.
// Each CTA owns HS=8 hidden elements => 32 gate rows of Whh, kept in registers.
// Per-step protocol: GEMV(h) -> gates -> STG h-slice into output buffer ->
// fence -> release-increment cnt[s] -> acquire-spin until all KCTA arrived ->
// reload full h row (L2, L1-bypassed) into smem.
__global__ void __launch_bounds__(NT, 1) k_lstm(
    const float* __restrict__ Pf, const float* __restrict__ Whhf,
    const float* __restrict__ h0f, const float* __restrict__ c0f,
    float* outf, int ldf, int colf, int flinf, int floutf, int* cntf,
    const float* __restrict__ Pb, const float* __restrict__ Whhb,
    const float* __restrict__ h0b, const float* __restrict__ c0b,
    float* outb, int ldb, int colb, int flinb, int floutb, int* cntb)
{
    int dir = blockIdx.x >= KCTA;
    int k   = blockIdx.x - dir * KCTA;
    const float* P   = dir ? Pb   : Pf;
    const float* Whh = dir ? Whhb : Whhf;
    const float* h0  = dir ? h0b  : h0f;
    const float* c0  = dir ? c0b  : c0f;
    float* outbase   = dir ? outb : outf;
    int ld    = dir ? ldb    : ldf;
    int col   = dir ? colb   : colf;
    int flin  = dir ? flinb  : flinf;
    int flout = dir ? floutb : floutf;
    int* cnt  = dir ? cntb   : cntf;

    __shared__ float h_s[416];   // padded to 13*32, tail zeroed
    __shared__ float z_s[32];    // gate-row partial sums (this CTA's 32 rows)
    __shared__ float c_s[HS];    // persistent cell state slice

    int tid = threadIdx.x, lane = tid & 31, w = tid >> 5;

    for (int i = tid; i < 416; i += NT) h_s[i] = (i < HH) ? h0[i] : 0.f;
    if (tid < HS) c_s[tid] = c0[k * HS + tid];

    // Whh slice -> registers: row li = w*RPW + r; gate q = li/8, elem m = li%8
    float wreg[RPW][13];
#pragma unroll
    for (int r = 0; r < RPW; r++) {
        int li = w * RPW + r; int q = li >> 3, m = li & 7;
        const float* wp = Whh + (q * 400 + k * HS + m) * 400;
#pragma unroll
        for (int j = 0; j < 13; j++) {
            int cc = j * 32 + lane;
            wreg[r][j] = (cc < 400) ? wp[cc] : 0.f;
        }
    }

    // x-projection prefetch (step 0)
    float x0 = 0, x1 = 0, x2 = 0, x3 = 0;
    if (tid < HS) {
        int row = flin ? (TT - 1) : 0;
        const float* pp = P + row * 1600 + k * HS + tid;
        x0 = pp[0]; x1 = pp[400]; x2 = pp[800]; x3 = pp[1200];
    }
    __syncthreads();

    for (int s = 0; s < TT; s++) {
        // prefetch next step's x-projection (hides DRAM latency behind the step)
        float nx0 = 0, nx1 = 0, nx2 = 0, nx3 = 0;
        if (tid < HS && s + 1 < TT) {
            int row = flin ? (TT - 2 - s) : (s + 1);
            const float* pp = P + row * 1600 + k * HS + tid;
            nx0 = pp[0]; nx1 = pp[400]; nx2 = pp[800]; nx3 = pp[1200];
        }

        // GEMV: 32 gate rows x 400 (weights in regs, h broadcast from smem)
        float acc[RPW] = {0.f, 0.f, 0.f, 0.f};
#pragma unroll
        for (int j = 0; j < 13; j++) {
            float hv = h_s[j * 32 + lane];
#pragma unroll
            for (int r = 0; r < RPW; r++) acc[r] += wreg[r][j] * hv;
        }
#pragma unroll
        for (int r = 0; r < RPW; r++) {
            float v = acc[r];
            v += __shfl_xor_sync(0xffffffffu, v, 16);
            v += __shfl_xor_sync(0xffffffffu, v, 8);
            v += __shfl_xor_sync(0xffffffffu, v, 4);
            v += __shfl_xor_sync(0xffffffffu, v, 2);
            v += __shfl_xor_sync(0xffffffffu, v, 1);
            if (lane == 0) z_s[w * RPW + r] = v;
        }
        __syncthreads();

        int orow = flout ? (TT - 1 - s) : s;
        float* outrow = outbase + orow * ld + col;

        if (tid < HS) {
            float zi = z_s[tid]      + x0;
            float zf = z_s[8 + tid]  + x1;
            float zg = z_s[16 + tid] + x2;
            float zo = z_s[24 + tid] + x3;
            float c = sigf(zf) * c_s[tid] + sigf(zi) * tanhff(zg);
            float h = sigf(zo) * tanhff(c);
            c_s[tid] = c;
            outrow[k * HS + tid] = h;
            __threadfence();
        }
        __syncthreads();

        if (tid == 0) {
            red_rel(&cnt[s]);
            while (ld_acq(&cnt[s]) < KCTA) { }
        }
        __syncthreads();

        // reload full new h (L1-bypassing: peer writes live in L2)
        for (int i = tid; i < HH; i += NT) h_s[i] = __ldcg(outrow + i);
        x0 = nx0; x1 = nx1; x2 = nx2; x3 = nx3;
        __syncthreads();
    }
}

// ---------------- launch ----------------
extern "C" void kernel_launch(void* const* d_in, const int* in_sizes, int n_in,
                              void* d_out, int out_size)
{
    const int*   word_seq   = (const int*)  d_in[0];
    const int*   pos_seq    = (const int*)  d_in[1];
    const int*   seg_ids    = (const int*)  d_in[2];
    const float* chem       = (const float*)d_in[3];
    const float* word_table = (const float*)d_in[4];
    const float* pos_table  = (const float*)d_in[5];
    const float* Ww         = (const float*)d_in[6];
    const float* Wb         = (const float*)d_in[7];
    const float* Wih1f = (const float*)d_in[8];
    const float* Whh1f = (const float*)d_in[9];
    const float* b1f   = (const float*)d_in[10];
    const float* h01f  = (const float*)d_in[11];
    const float* c01f  = (const float*)d_in[12];
    const float* Wih1b = (const float*)d_in[13];
    const float* Whh1b = (const float*)d_in[14];
    const float* b1b   = (const float*)d_in[15];
    const float* h01b  = (const float*)d_in[16];
    const float* c01b  = (const float*)d_in[17];
    const float* Wih2f = (const float*)d_in[18];
    const float* Whh2f = (const float*)d_in[19];
    const float* b2f   = (const float*)d_in[20];
    const float* h02f  = (const float*)d_in[21];
    const float* c02f  = (const float*)d_in[22];
    const float* Wih2b = (const float*)d_in[23];
    const float* Whh2b = (const float*)d_in[24];
    const float* b2b   = (const float*)d_in[25];
    const float* h02b  = (const float*)d_in[26];
    const float* c02b  = (const float*)d_in[27];

    float* out = (float*)d_out;

    float *ef, *l1, *PF, *PB, *meanp; int* cnt;
    cudaGetSymbolAddress((void**)&ef,    g_ef);
    cudaGetSymbolAddress((void**)&l1,    g_l1);
    cudaGetSymbolAddress((void**)&PF,    g_PF);
    cudaGetSymbolAddress((void**)&PB,    g_PB);
    cudaGetSymbolAddress((void**)&meanp, g_mean);
    cudaGetSymbolAddress((void**)&cnt,   g_cnt);

    // prep
    k_zero_cnt<<<(4 * TT + 255) / 256, 256>>>();
    k_starts<<<(NCHARS + 255) / 256, 256>>>(seg_ids);
    k_mean<<<TT, 256>>>(chem);
    k_pos<<<(TT * 100 + 255) / 256, 256>>>(pos_seq, pos_table);

    // wc = tanh(word_table[word_seq] @ Ww.T + Wb) + chars_mean  -> ef[:, :768]
    k_gemm<<<dim3(12, 63, 1), 256>>>(TT, 768, 300,
        word_table, 300, word_seq,
        Ww, Wb, ef, nullptr, nullptr, nullptr,
        868, meanp, 1);

    // layer-1 input projections (both directions, unflipped rows)
    k_gemm<<<dim3(25, 63, 2), 256>>>(TT, 1600, 868,
        ef, 868, nullptr,
        Wih1f, b1f, PF,
        Wih1b, b1b, PB,
        1600, nullptr, 0);

    // layer-1 recurrence: fwd -> l1[:, :400]; bwd (flipped in & out) -> l1[:, 400:800]
    k_lstm<<<2 * KCTA, NT>>>(
        PF, Whh1f, h01f, c01f, l1, 800, 0,   0, 0, cnt + 0 * TT,
        PB, Whh1b, h01b, c01b, l1, 800, 400, 1, 1, cnt + 1 * TT);

    // layer-2 input projections on l1
    k_gemm<<<dim3(25, 63, 2), 256>>>(TT, 1600, 800,
        l1, 800, nullptr,
        Wih2f, b2f, PF,
        Wih2b, b2b, PB,
        1600, nullptr, 0);

    // layer-2 recurrence: f1b -> out[0:T*400]; f2b (scan order, flipped input) -> out[T*400:]
    k_lstm<<<2 * KCTA, NT>>>(
        PF, Whh2f, h02f, c02f, out,            400, 0, 0, 0, cnt + 2 * TT,
        PB, Whh2b, h02b, c02b, out + TT * 400, 400, 0, 1, 0, cnt + 3 * TT);
}

// round 2
// speedup vs baseline: 1.0501x; 1.0501x over previous
#include <cuda_runtime.h>
#include <math.h>

// ---------------- problem constants ----------------
#define TT      4000          // N_WORDS (sequence length)
#define NCHARS  16000
#define DCHAR   768
#define HH      400           // hidden size
#define KCTA    50            // CTAs per LSTM direction
#define HS      8             // h elements per CTA (400/50)
#define RPW     4             // gate rows per warp (32 rows / 8 warps)
#define NT      256           // threads per CTA

// ---------------- device scratch (static, no allocation) ----------------
__device__ float g_ef[TT * 868];        // [wc(768) | pos(100)]
__device__ float g_l1[TT * 800];        // layer-1 output [f1 | flip(f2)]
__device__ float g_PF[TT * 1600];       // x-projection, forward dir
__device__ float g_PB[TT * 1600];       // x-projection, backward dir
__device__ float g_mean[TT * DCHAR];    // chars_mean
__device__ int   g_starts[TT + 1];
// tagged h broadcast buffers: 4 sets (F1,B1,F2,B2) x 2 parities x 400
__device__ unsigned long long g_hb[4 * 2 * HH];

// ---------------- small prep kernels ----------------
__global__ void k_zero() {
    int i = blockIdx.x * blockDim.x + threadIdx.x;
    if (i < 4 * 2 * HH) g_hb[i] = 0ULL;
}

__global__ void k_starts(const int* __restrict__ seg) {
    int i = blockIdx.x * blockDim.x + threadIdx.x;
    if (i < NCHARS) {
        if (i == 0 || seg[i] != seg[i - 1]) g_starts[seg[i]] = i;
    }
    if (i == 0) g_starts[TT] = NCHARS;
}

__global__ void k_mean(const float* __restrict__ chem) {
    int w = blockIdx.x;
    int s = g_starts[w], e = g_starts[w + 1];
    float inv = 1.f / (float)(e - s);
    for (int d = threadIdx.x; d < DCHAR; d += blockDim.x) {
        float acc = 0.f;
        for (int r = s; r < e; r++) acc += chem[(r + 1) * DCHAR + d];
        g_mean[w * DCHAR + d] = acc * inv;
    }
}

__global__ void k_pos(const int* __restrict__ pos_seq, const float* __restrict__ pos_table) {
    int i = blockIdx.x * blockDim.x + threadIdx.x;
    if (i < TT * 100) {
        int m = i / 100, j = i % 100;
        g_ef[m * 868 + 768 + j] = pos_table[pos_seq[m] * 100 + j];
    }
}

// ---------------- fp32 GEMM: C[m,n] = dot(A[m,:], B[n,:]) + bias[n] ----------------
// 128x128x16 tiles, 256 threads, 8x8 microtile, float4 global loads.
// blockIdx.z selects weight set. mode==1: C = tanh(acc+bias) + extra[m*768+n].
__global__ void __launch_bounds__(256, 2) k_gemm(
    int M, int N, int Ka,
    const float* __restrict__ A, int lda, const int* __restrict__ Aidx,
    const float* __restrict__ B0, const float* __restrict__ bias0, float* __restrict__ C0,
    const float* __restrict__ B1, const float* __restrict__ bias1, float* __restrict__ C1,
    int ldc, const float* __restrict__ extra, int mode)
{
    const float* B    = blockIdx.z ? B1    : B0;
    const float* bias = blockIdx.z ? bias1 : bias0;
    float*       C    = blockIdx.z ? C1    : C0;

    __shared__ float As[16][132];
    __shared__ float Bs[16][132];
    int tid = threadIdx.x;
    int tx = tid & 15, ty = tid >> 4;
    int m0 = blockIdx.y * 128, n0 = blockIdx.x * 128;

    int lr = tid >> 2;          // 0..63
    int lk = (tid & 3) * 4;     // 0,4,8,12

    float acc[8][8];
#pragma unroll
    for (int i = 0; i < 8; i++)
#pragma unroll
        for (int j = 0; j < 8; j++) acc[i][j] = 0.f;

    for (int kt = 0; kt < Ka; kt += 16) {
#pragma unroll
        for (int p = 0; p < 2; p++) {       // A tile
            int m = lr + p * 64; int gm = m0 + m;
            float4 v = make_float4(0.f, 0.f, 0.f, 0.f);
            if (gm < M && kt + lk < Ka) {
                int ar = Aidx ? Aidx[gm] : gm;
                v = *(const float4*)&A[(size_t)ar * lda + kt + lk];
            }
            As[lk + 0][m] = v.x; As[lk + 1][m] = v.y;
            As[lk + 2][m] = v.z; As[lk + 3][m] = v.w;
        }
#pragma unroll
        for (int p = 0; p < 2; p++) {       // B tile
            int n = lr + p * 64; int gn = n0 + n;
            float4 v = make_float4(0.f, 0.f, 0.f, 0.f);
            if (gn < N && kt + lk < Ka) {
                v = *(const float4*)&B[(size_t)gn * Ka + kt + lk];
            }
            Bs[lk + 0][n] = v.x; Bs[lk + 1][n] = v.y;
            Bs[lk + 2][n] = v.z; Bs[lk + 3][n] = v.w;
        }
        __syncthreads();
#pragma unroll
        for (int kk = 0; kk < 16; kk++) {
            float a[8], b[8];
            *(float4*)&a[0] = *(const float4*)&As[kk][ty * 8];
            *(float4*)&a[4] = *(const float4*)&As[kk][ty * 8 + 4];
            *(float4*)&b[0] = *(const float4*)&Bs[kk][tx * 8];
            *(float4*)&b[4] = *(const float4*)&Bs[kk][tx * 8 + 4];
#pragma unroll
            for (int i = 0; i < 8; i++)
#pragma unroll
                for (int j = 0; j < 8; j++) acc[i][j] += a[i] * b[j];
        }
        __syncthreads();
    }
#pragma unroll
    for (int i = 0; i < 8; i++) {
        int m = m0 + ty * 8 + i;
        if (m < M) {
#pragma unroll
            for (int j = 0; j < 8; j++) {
                int n = n0 + tx * 8 + j;
                if (n < N) {
                    float v = acc[i][j] + bias[n];
                    if (mode == 1) v = tanhf(v) + extra[(size_t)m * DCHAR + n];
                    C[(size_t)m * ldc + n] = v;
                }
            }
        }
    }
}

// ---------------- persistent bidirectional LSTM recurrence ----------------
__device__ __forceinline__ float sigf(float x)  { return 1.f / (1.f + __expf(-x)); }
__device__ __forceinline__ float tanhff(float x){ return 2.f / (1.f + __expf(-2.f * x)) - 1.f; }

// grid = 2*KCTA CTAs (fwd then bwd direction), all co-resident.
// Per-step sync is fused into the data: each h element published as one
// relaxed 64-bit store packing (tag = s+1, h). Consumers spin on the tag.
// Double-buffered by step parity; safety: a buffer is only reused 2 steps
// later, and writing step s+2 requires having consumed step s+1, which
// requires everyone consumed step s.
__global__ void __launch_bounds__(NT, 1) k_lstm(
    const float* __restrict__ Pf, const float* __restrict__ Whhf,
    const float* __restrict__ h0f, const float* __restrict__ c0f,
    float* outf, int ldf, int colf, int flinf, int floutf, unsigned long long* hbf,
    const float* __restrict__ Pb, const float* __restrict__ Whhb,
    const float* __restrict__ h0b, const float* __restrict__ c0b,
    float* outb, int ldb, int colb, int flinb, int floutb, unsigned long long* hbb)
{
    int dir = blockIdx.x >= KCTA;
    int k   = blockIdx.x - dir * KCTA;
    const float* P   = dir ? Pb   : Pf;
    const float* Whh = dir ? Whhb : Whhf;
    const float* h0  = dir ? h0b  : h0f;
    const float* c0  = dir ? c0b  : c0f;
    float* outbase   = dir ? outb : outf;
    int ld    = dir ? ldb    : ldf;
    int col   = dir ? colb   : colf;
    int flin  = dir ? flinb  : flinf;
    int flout = dir ? floutb : floutf;
    unsigned long long* hb = dir ? hbb : hbf;

    __shared__ float h_s[416];   // padded to 13*32, tail zeroed
    __shared__ float z_s[32];    // this CTA's 32 gate-row sums

    int tid = threadIdx.x, lane = tid & 31, w = tid >> 5;

    for (int i = tid; i < 416; i += NT) h_s[i] = (i < HH) ? h0[i] : 0.f;
    float creg = (tid < HS) ? c0[k * HS + tid] : 0.f;

    // Whh slice -> registers: row li = w*RPW + r; gate q = li/8, elem m = li%8
    float wreg[RPW][13];
#pragma unroll
    for (int r = 0; r < RPW; r++) {
        int li = w * RPW + r; int q = li >> 3, m = li & 7;
        const float* wp = Whh + (size_t)(q * 400 + k * HS + m) * 400;
#pragma unroll
        for (int j = 0; j < 13; j++) {
            int cc = j * 32 + lane;
            wreg[r][j] = (cc < 400) ? wp[cc] : 0.f;
        }
    }

    // x-projection prefetch (step 0)
    float x0 = 0, x1 = 0, x2 = 0, x3 = 0;
    if (tid < HS) {
        int row = flin ? (TT - 1) : 0;
        const float* pp = P + (size_t)row * 1600 + k * HS + tid;
        x0 = pp[0]; x1 = pp[400]; x2 = pp[800]; x3 = pp[1200];
    }
    __syncthreads();

    for (int s = 0; s < TT; s++) {
        // prefetch next step's x-projection
        float nx0 = 0, nx1 = 0, nx2 = 0, nx3 = 0;
        if (tid < HS && s + 1 < TT) {
            int row = flin ? (TT - 2 - s) : (s + 1);
            const float* pp = P + (size_t)row * 1600 + k * HS + tid;
            nx0 = pp[0]; nx1 = pp[400]; nx2 = pp[800]; nx3 = pp[1200];
        }

        // GEMV: 32 gate rows x 400 (weights in regs, h broadcast from smem)
        float acc[RPW] = {0.f, 0.f, 0.f, 0.f};
#pragma unroll
        for (int j = 0; j < 13; j++) {
            float hv = h_s[j * 32 + lane];
#pragma unroll
            for (int r = 0; r < RPW; r++) acc[r] += wreg[r][j] * hv;
        }
#pragma unroll
        for (int r = 0; r < RPW; r++) {
            float v = acc[r];
            v += __shfl_xor_sync(0xffffffffu, v, 16);
            v += __shfl_xor_sync(0xffffffffu, v, 8);
            v += __shfl_xor_sync(0xffffffffu, v, 4);
            v += __shfl_xor_sync(0xffffffffu, v, 2);
            v += __shfl_xor_sync(0xffffffffu, v, 1);
            if (lane == 0) z_s[w * RPW + r] = v;
        }
        __syncthreads();   // z_s ready; h_s no longer needed

        int orow = flout ? (TT - 1 - s) : s;
        float* outrow = outbase + (size_t)orow * ld + col;

        if (tid < HS) {
            float zi = z_s[tid]      + x0;
            float zf = z_s[8 + tid]  + x1;
            float zg = z_s[16 + tid] + x2;
            float zo = z_s[24 + tid] + x3;
            float c = sigf(zf) * creg + sigf(zi) * tanhff(zg);
            float h = sigf(zo) * tanhff(c);
            creg = c;
            h_s[k * HS + tid] = h;               // own slice -> smem directly
            outrow[k * HS + tid] = h;            // layer output (off critical path)
            unsigned long long pk =
                ((unsigned long long)(unsigned)(s + 1) << 32) |
                (unsigned long long)__float_as_uint(h);
            unsigned long long* dst = hb + (size_t)(s & 1) * HH + k * HS + tid;
            asm volatile("st.relaxed.gpu.global.b64 [%0], %1;" :: "l"(dst), "l"(pk) : "memory");
        }

        if (s + 1 < TT) {
            // consume: spin on tags, payload rides in the same 8 bytes
            const unsigned long long* src = hb + (size_t)(s & 1) * HH;
            unsigned tgt = (unsigned)(s + 1);
            int lo = k * HS, hi = k * HS + HS;
            for (int i = tid; i < HH; i += NT) {
                if (i >= lo && i < hi) continue;   // own slice already in smem
                unsigned long long v;
                do {
                    asm volatile("ld.relaxed.gpu.global.b64 %0, [%1];"
                                 : "=l"(v) : "l"(src + i) : "memory");
                } while ((unsigned)(v >> 32) != tgt);
                h_s[i] = __uint_as_float((unsigned)v);
            }
            x0 = nx0; x1 = nx1; x2 = nx2; x3 = nx3;
            __syncthreads();   // h_s complete before next GEMV
        }
    }
}

// ---------------- launch ----------------
extern "C" void kernel_launch(void* const* d_in, const int* in_sizes, int n_in,
                              void* d_out, int out_size)
{
    const int*   word_seq   = (const int*)  d_in[0];
    const int*   pos_seq    = (const int*)  d_in[1];
    const int*   seg_ids    = (const int*)  d_in[2];
    const float* chem       = (const float*)d_in[3];
    const float* word_table = (const float*)d_in[4];
    const float* pos_table  = (const float*)d_in[5];
    const float* Ww         = (const float*)d_in[6];
    const float* Wb         = (const float*)d_in[7];
    const float* Wih1f = (const float*)d_in[8];
    const float* Whh1f = (const float*)d_in[9];
    const float* b1f   = (const float*)d_in[10];
    const float* h01f  = (const float*)d_in[11];
    const float* c01f  = (const float*)d_in[12];
    const float* Wih1b = (const float*)d_in[13];
    const float* Whh1b = (const float*)d_in[14];
    const float* b1b   = (const float*)d_in[15];
    const float* h01b  = (const float*)d_in[16];
    const float* c01b  = (const float*)d_in[17];
    const float* Wih2f = (const float*)d_in[18];
    const float* Whh2f = (const float*)d_in[19];
    const float* b2f   = (const float*)d_in[20];
    const float* h02f  = (const float*)d_in[21];
    const float* c02f  = (const float*)d_in[22];
    const float* Wih2b = (const float*)d_in[23];
    const float* Whh2b = (const float*)d_in[24];
    const float* b2b   = (const float*)d_in[25];
    const float* h02b  = (const float*)d_in[26];
    const float* c02b  = (const float*)d_in[27];

    float* out = (float*)d_out;

    float *ef, *l1, *PF, *PB, *meanp; unsigned long long* hb;
    cudaGetSymbolAddress((void**)&ef,    g_ef);
    cudaGetSymbolAddress((void**)&l1,    g_l1);
    cudaGetSymbolAddress((void**)&PF,    g_PF);
    cudaGetSymbolAddress((void**)&PB,    g_PB);
    cudaGetSymbolAddress((void**)&meanp, g_mean);
    cudaGetSymbolAddress((void**)&hb,    g_hb);

    // prep
    k_zero<<<(4 * 2 * HH + 255) / 256, 256>>>();
    k_starts<<<(NCHARS + 255) / 256, 256>>>(seg_ids);
    k_mean<<<TT, 256>>>(chem);
    k_pos<<<(TT * 100 + 255) / 256, 256>>>(pos_seq, pos_table);

    // wc = tanh(word_table[word_seq] @ Ww.T + Wb) + chars_mean  -> ef[:, :768]
    k_gemm<<<dim3(6, 32, 1), 256>>>(TT, 768, 300,
        word_table, 300, word_seq,
        Ww, Wb, ef, nullptr, nullptr, nullptr,
        868, meanp, 1);

    // layer-1 input projections (both directions)
    k_gemm<<<dim3(13, 32, 2), 256>>>(TT, 1600, 868,
        ef, 868, nullptr,
        Wih1f, b1f, PF,
        Wih1b, b1b, PB,
        1600, nullptr, 0);

    // layer-1 recurrence: fwd -> l1[:, :400]; bwd (flip in&out) -> l1[:, 400:800]
    k_lstm<<<2 * KCTA, NT>>>(
        PF, Whh1f, h01f, c01f, l1, 800, 0,   0, 0, hb + 0 * 2 * HH,
        PB, Whh1b, h01b, c01b, l1, 800, 400, 1, 1, hb + 1 * 2 * HH);

    // layer-2 input projections on l1
    k_gemm<<<dim3(13, 32, 2), 256>>>(TT, 1600, 800,
        l1, 800, nullptr,
        Wih2f, b2f, PF,
        Wih2b, b2b, PB,
        1600, nullptr, 0);

    // layer-2 recurrence: f1b -> out[0:T*400]; f2b (scan order, flipped input)
    k_lstm<<<2 * KCTA, NT>>>(
        PF, Whh2f, h02f, c02f, out,            400, 0, 0, 0, hb + 2 * 2 * HH,
        PB, Whh2b, h02b, c02b, out + (size_t)TT * 400, 400, 0, 1, 0, hb + 3 * 2 * HH);
}

// round 4
// speedup vs baseline: 1.6592x; 1.5801x over previous
#include <cuda_runtime.h>
#include <math.h>

// ---------------- problem constants ----------------
#define TT      4000          // N_WORDS (sequence length)
#define NCHARS  16000
#define DCHAR   768
#define HH      400           // hidden size
#define KCTA    50            // CTAs per LSTM direction
#define HS      8             // h elements per CTA (one per warp)
#define NT      256           // threads per CTA

// ---------------- device scratch (static, no allocation) ----------------
__device__ float g_ef[TT * 868];        // [wc(768) | pos(100)]
__device__ float g_l1[TT * 800];        // layer-1 output [f1 | flip(f2)]
__device__ float g_PF[TT * 1600];       // x-projection, forward dir
__device__ float g_PB[TT * 1600];       // x-projection, backward dir
__device__ float g_mean[TT * DCHAR];    // chars_mean
// tagged h broadcast: 4 sets (F1,B1,F2,B2) x 2 parities x 400 elements
__device__ __align__(16) unsigned long long g_hb[4 * 2 * HH];

// ---------------- k_mean: binary-search starts + segment mean + zero g_hb ----
__global__ void k_mean(const float* __restrict__ chem, const int* __restrict__ seg) {
    int w = blockIdx.x, tid = threadIdx.x;

    // fold in: zero the broadcast buffers (blocks 0..12)
    if (w < 13) {
        int i = w * 256 + tid;
        if (i < 4 * 2 * HH) g_hb[i] = 0ULL;
    }

    __shared__ int se[2];
    if (tid < 2) {
        int target = w + tid;               // lower_bound(seg, target)
        int lo = 0, hi = NCHARS;
        while (lo < hi) { int m = (lo + hi) >> 1; if (seg[m] < target) lo = m + 1; else hi = m; }
        se[tid] = lo;
    }
    __syncthreads();
    int s = se[0], e = se[1];
    float inv = 1.f / (float)(e - s);
    for (int d = tid; d < DCHAR; d += blockDim.x) {
        float acc = 0.f;
        for (int r = s; r < e; r++) acc += chem[(size_t)(r + 1) * DCHAR + d];
        g_mean[(size_t)w * DCHAR + d] = acc * inv;
    }
}

// ---------------- fp32 GEMM: C[m,n] = dot(A[m,:], B[n,:]) + bias[n] ----------------
// 128x128x16 tiles, 256 threads, 8x8 microtile, float4 global loads.
// blockIdx.z selects weight set. mode==1: C = tanh(acc+bias) + extra[m*768+n],
// and blockIdx.z==1 blocks instead do the pos-table gather into g_ef[:,768:868].
__global__ void __launch_bounds__(256, 2) k_gemm(
    int M, int N, int Ka,
    const float* __restrict__ A, int lda, const int* __restrict__ Aidx,
    const float* __restrict__ B0, const float* __restrict__ bias0, float* __restrict__ C0,
    const float* __restrict__ B1, const float* __restrict__ bias1, float* __restrict__ C1,
    int ldc, const float* __restrict__ extra, int mode,
    const int* __restrict__ pos_seq, const float* __restrict__ pos_table)
{
    if (mode == 1 && blockIdx.z == 1) {
        // pos fill: g_ef[m*868 + 768 + j] = pos_table[pos_seq[m]*100 + j]
        int nb = gridDim.x * gridDim.y;
        int bid = blockIdx.y * gridDim.x + blockIdx.x;
        for (int i = bid * 256 + threadIdx.x; i < TT * 100; i += nb * 256) {
            int m = i / 100, j = i - m * 100;
            g_ef[(size_t)m * 868 + 768 + j] = pos_table[pos_seq[m] * 100 + j];
        }
        return;
    }

    const float* B    = blockIdx.z ? B1    : B0;
    const float* bias = blockIdx.z ? bias1 : bias0;
    float*       C    = blockIdx.z ? C1    : C0;

    __shared__ float As[16][132];
    __shared__ float Bs[16][132];
    int tid = threadIdx.x;
    int tx = tid & 15, ty = tid >> 4;
    int m0 = blockIdx.y * 128, n0 = blockIdx.x * 128;

    int lr = tid >> 2;          // 0..63
    int lk = (tid & 3) * 4;     // 0,4,8,12

    float acc[8][8];
#pragma unroll
    for (int i = 0; i < 8; i++)
#pragma unroll
        for (int j = 0; j < 8; j++) acc[i][j] = 0.f;

    for (int kt = 0; kt < Ka; kt += 16) {
#pragma unroll
        for (int p = 0; p < 2; p++) {       // A tile
            int m = lr + p * 64; int gm = m0 + m;
            float4 v = make_float4(0.f, 0.f, 0.f, 0.f);
            if (gm < M && kt + lk < Ka) {
                int ar = Aidx ? Aidx[gm] : gm;
                v = *(const float4*)&A[(size_t)ar * lda + kt + lk];
            }
            As[lk + 0][m] = v.x; As[lk + 1][m] = v.y;
            As[lk + 2][m] = v.z; As[lk + 3][m] = v.w;
        }
#pragma unroll
        for (int p = 0; p < 2; p++) {       // B tile
            int n = lr + p * 64; int gn = n0 + n;
            float4 v = make_float4(0.f, 0.f, 0.f, 0.f);
            if (gn < N && kt + lk < Ka) {
                v = *(const float4*)&B[(size_t)gn * Ka + kt + lk];
            }
            Bs[lk + 0][n] = v.x; Bs[lk + 1][n] = v.y;
            Bs[lk + 2][n] = v.z; Bs[lk + 3][n] = v.w;
        }
        __syncthreads();
#pragma unroll
        for (int kk = 0; kk < 16; kk++) {
            float a[8], b[8];
            *(float4*)&a[0] = *(const float4*)&As[kk][ty * 8];
            *(float4*)&a[4] = *(const float4*)&As[kk][ty * 8 + 4];
            *(float4*)&b[0] = *(const float4*)&Bs[kk][tx * 8];
            *(float4*)&b[4] = *(const float4*)&Bs[kk][tx * 8 + 4];
#pragma unroll
            for (int i = 0; i < 8; i++)
#pragma unroll
                for (int j = 0; j < 8; j++) acc[i][j] += a[i] * b[j];
        }
        __syncthreads();
    }
#pragma unroll
    for (int i = 0; i < 8; i++) {
        int m = m0 + ty * 8 + i;
        if (m < M) {
#pragma unroll
            for (int j = 0; j < 8; j++) {
                int n = n0 + tx * 8 + j;
                if (n < N) {
                    float v = acc[i][j] + bias[n];
                    if (mode == 1) v = tanhf(v) + extra[(size_t)m * DCHAR + n];
                    C[(size_t)m * ldc + n] = v;
                }
            }
        }
    }
}

// ---------------- persistent bidirectional LSTM recurrence ----------------
// Warp w of CTA k owns hidden element e = k*8 + w (all 4 gate rows).
// Butterfly allreduce leaves all lanes with the 4 gate sums; lanes 0-3 each
// apply one gate nonlinearity in parallel; lane 0 forms (c,h) and publishes
// a tagged 8B packet via relaxed L2 store BEFORE any barrier. 200 pollers
// fetch 2 elements each with concurrent relaxed loads. One bar per step.
__global__ void __launch_bounds__(NT, 1) k_lstm(
    const float* __restrict__ Pf, const float* __restrict__ Whhf,
    const float* __restrict__ h0f, const float* __restrict__ c0f,
    float* outf, int ldf, int colf, int flinf, int floutf, unsigned long long* hbf,
    const float* __restrict__ Pb, const float* __restrict__ Whhb,
    const float* __restrict__ h0b, const float* __restrict__ c0b,
    float* outb, int ldb, int colb, int flinb, int floutb, unsigned long long* hbb)
{
    int dir = blockIdx.x >= KCTA;
    int k   = blockIdx.x - dir * KCTA;
    const float* P   = dir ? Pb   : Pf;
    const float* Whh = dir ? Whhb : Whhf;
    const float* h0  = dir ? h0b  : h0f;
    const float* c0  = dir ? c0b  : c0f;
    float* outbase   = dir ? outb : outf;
    int ld    = dir ? ldb    : ldf;
    int col   = dir ? colb   : colf;
    int flin  = dir ? flinb  : flinf;
    int flout = dir ? floutb : floutf;
    unsigned long long* hb = dir ? hbb : hbf;

    __shared__ float hbuf[2][416];   // double-buffered h (tail zero)

    int tid = threadIdx.x, lane = tid & 31, w = tid >> 5;
    int e = k * HS + w;              // global hidden element owned by this warp

    for (int i = tid; i < 416; i += NT) {
        hbuf[0][i] = (i < HH) ? h0[i] : 0.f;
        hbuf[1][i] = 0.f;
    }
    float creg = 0.f;
    if (lane == 0) creg = c0[e];

    // Whh rows (4 gates of element e) -> registers
    float wreg[4][13];
#pragma unroll
    for (int q = 0; q < 4; q++) {
        const float* wp = Whh + (size_t)(q * HH + e) * HH;
#pragma unroll
        for (int j = 0; j < 13; j++) {
            int cc = j * 32 + lane;
            wreg[q][j] = (cc < HH) ? wp[cc] : 0.f;
        }
    }

    // x-projection for step 0: lane q (q<4) holds gate-q term
    float xcur = 0.f;
    if (lane < 4) {
        int row = flin ? (TT - 1) : 0;
        xcur = P[(size_t)row * 1600 + lane * HH + e];
    }
    __syncthreads();

    for (int s = 0; s < TT; s++) {
        // prefetch next step's x
        float xn = 0.f;
        if (lane < 4 && s + 1 < TT) {
            int row = flin ? (TT - 2 - s) : (s + 1);
            xn = P[(size_t)row * 1600 + lane * HH + e];
        }

        const float* cur = hbuf[s & 1];
        float* nxt = hbuf[(s + 1) & 1];

        // GEMV: 4 gate rows x 400, weights in regs, h from smem
        float a0 = 0.f, a1 = 0.f, a2 = 0.f, a3 = 0.f;
#pragma unroll
        for (int j = 0; j < 13; j++) {
            float hv = cur[j * 32 + lane];
            a0 += wreg[0][j] * hv;
            a1 += wreg[1][j] * hv;
            a2 += wreg[2][j] * hv;
            a3 += wreg[3][j] * hv;
        }
        // butterfly allreduce (all lanes end with full sums)
#pragma unroll
        for (int d = 16; d > 0; d >>= 1) {
            a0 += __shfl_xor_sync(0xffffffffu, a0, d);
            a1 += __shfl_xor_sync(0xffffffffu, a1, d);
            a2 += __shfl_xor_sync(0xffffffffu, a2, d);
            a3 += __shfl_xor_sync(0xffffffffu, a3, d);
        }

        // lane q (0..3) applies gate-q nonlinearity (others compute junk)
        float zsel = (lane & 2) ? ((lane & 1) ? a3 : a2)
                                : ((lane & 1) ? a1 : a0);
        float z = zsel + xcur;
        float earg = (lane == 2) ? (-2.f * z) : (-z);
        float r = 1.f / (1.f + __expf(earg));
        float nl = (lane == 2) ? (2.f * r - 1.f) : r;   // tanh for g, sigmoid else

        float gi = __shfl_sync(0xffffffffu, nl, 0);
        float gf = __shfl_sync(0xffffffffu, nl, 1);
        float gg = __shfl_sync(0xffffffffu, nl, 2);
        float go = __shfl_sync(0xffffffffu, nl, 3);

        int orow = flout ? (TT - 1 - s) : s;
        if (lane == 0) {
            float c = gf * creg + gi * gg;
            creg = c;
            float th = 2.f / (1.f + __expf(-2.f * c)) - 1.f;
            float h = go * th;
            outbase[(size_t)orow * ld + col + e] = h;   // layer output
            if (s + 1 < TT) {
                nxt[e] = h;                              // own slice locally
                unsigned long long pk =
                    ((unsigned long long)(unsigned)(s + 1) << 32) |
                    (unsigned long long)__float_as_uint(h);
                unsigned long long* dst = hb + (size_t)(s & 1) * HH + e;
                asm volatile("st.relaxed.gpu.global.b64 [%0], %1;"
                             :: "l"(dst), "l"(pk) : "memory");
            }
        }

        // consume: 200 pollers, 2 elements each, both loads in flight
        if (s + 1 < TT && tid < 200 && (tid < k * 4 || tid >= k * 4 + 4)) {
            const unsigned long long* sp = hb + (size_t)(s & 1) * HH + 2 * tid;
            unsigned tgt = (unsigned)(s + 1);
            unsigned long long v0, v1;
            for (;;) {
                asm volatile("ld.relaxed.gpu.global.b64 %0, [%2];\n\t"
                             "ld.relaxed.gpu.global.b64 %1, [%2+8];"
                             : "=l"(v0), "=l"(v1) : "l"(sp) : "memory");
                if ((unsigned)(v0 >> 32) == tgt && (unsigned)(v1 >> 32) == tgt) break;
            }
            nxt[2 * tid]     = __uint_as_float((unsigned)v0);
            nxt[2 * tid + 1] = __uint_as_float((unsigned)v1);
        }
        xcur = xn;
        __syncthreads();   // nxt complete before next GEMV
    }
}

// ---------------- launch ----------------
extern "C" void kernel_launch(void* const* d_in, const int* in_sizes, int n_in,
                              void* d_out, int out_size)
{
    const int*   word_seq   = (const int*)  d_in[0];
    const int*   pos_seq    = (const int*)  d_in[1];
    const int*   seg_ids    = (const int*)  d_in[2];
    const float* chem       = (const float*)d_in[3];
    const float* word_table = (const float*)d_in[4];
    const float* pos_table  = (const float*)d_in[5];
    const float* Ww         = (const float*)d_in[6];
    const float* Wb         = (const float*)d_in[7];
    const float* Wih1f = (const float*)d_in[8];
    const float* Whh1f = (const float*)d_in[9];
    const float* b1f   = (const float*)d_in[10];
    const float* h01f  = (const float*)d_in[11];
    const float* c01f  = (const float*)d_in[12];
    const float* Wih1b = (const float*)d_in[13];
    const float* Whh1b = (const float*)d_in[14];
    const float* b1b   = (const float*)d_in[15];
    const float* h01b  = (const float*)d_in[16];
    const float* c01b  = (const float*)d_in[17];
    const float* Wih2f = (const float*)d_in[18];
    const float* Whh2f = (const float*)d_in[19];
    const float* b2f   = (const float*)d_in[20];
    const float* h02f  = (const float*)d_in[21];
    const float* c02f  = (const float*)d_in[22];
    const float* Wih2b = (const float*)d_in[23];
    const float* Whh2b = (const float*)d_in[24];
    const float* b2b   = (const float*)d_in[25];
    const float* h02b  = (const float*)d_in[26];
    const float* c02b  = (const float*)d_in[27];

    float* out = (float*)d_out;

    float *ef, *l1, *PF, *PB, *meanp; unsigned long long* hb;
    cudaGetSymbolAddress((void**)&ef,    g_ef);
    cudaGetSymbolAddress((void**)&l1,    g_l1);
    cudaGetSymbolAddress((void**)&PF,    g_PF);
    cudaGetSymbolAddress((void**)&PB,    g_PB);
    cudaGetSymbolAddress((void**)&meanp, g_mean);
    cudaGetSymbolAddress((void**)&hb,    g_hb);

    // (0) mean + starts(bsearch) + hb zero
    k_mean<<<TT, 256>>>(chem, seg_ids);

    // (1) wc = tanh(word_e @ Ww.T + Wb) + mean -> ef[:, :768]; z=1 blocks do pos fill
    k_gemm<<<dim3(6, 32, 2), 256>>>(TT, 768, 300,
        word_table, 300, word_seq,
        Ww, Wb, ef, nullptr, nullptr, nullptr,
        868, meanp, 1, pos_seq, pos_table);

    // (2) layer-1 input projections (both directions)
    k_gemm<<<dim3(13, 32, 2), 256>>>(TT, 1600, 868,
        ef, 868, nullptr,
        Wih1f, b1f, PF,
        Wih1b, b1b, PB,
        1600, nullptr, 0, nullptr, nullptr);

    // (3) layer-1 recurrence
    k_lstm<<<2 * KCTA, NT>>>(
        PF, Whh1f, h01f, c01f, l1, 800, 0,   0, 0, hb + 0 * 2 * HH,
        PB, Whh1b, h01b, c01b, l1, 800, 400, 1, 1, hb + 1 * 2 * HH);

    // (4) layer-2 input projections on l1
    k_gemm<<<dim3(13, 32, 2), 256>>>(TT, 1600, 800,
        l1, 800, nullptr,
        Wih2f, b2f, PF,
        Wih2b, b2b, PB,
        1600, nullptr, 0, nullptr, nullptr);

    // (5) layer-2 recurrence
    k_lstm<<<2 * KCTA, NT>>>(
        PF, Whh2f, h02f, c02f, out,                    400, 0, 0, 0, hb + 2 * 2 * HH,
        PB, Whh2b, h02b, c02b, out + (size_t)TT * 400, 400, 0, 1, 0, hb + 3 * 2 * HH);
}